// round 1
// baseline (speedup 1.0000x reference)
#include <cuda_runtime.h>

// BinNormTrain: per-row, find nu s.t. sum_d sigmoid(x[d]+nu) == K, output sigmoid(x+nu).
// Reference converges its bracket to width ~6.8e-5 (EPS=1e-4); its nu is within
// 3.4e-5 of the true root. Relative error of sigmoid under a nu-shift d is <= d
// (uniformly, all magnitudes), so solving the root to ~1e-6 via safeguarded
// Newton reproduces the reference to ~4e-5 relative, far under the 1e-3 gate.

#ifndef BN_D
#define BN_D 256
#endif

static __device__ __forceinline__ float warp_sum(float v) {
    #pragma unroll
    for (int o = 16; o > 0; o >>= 1) v += __shfl_xor_sync(0xFFFFFFFFu, v, o);
    return v;
}
static __device__ __forceinline__ float warp_max(float v) {
    #pragma unroll
    for (int o = 16; o > 0; o >>= 1) v = fmaxf(v, __shfl_xor_sync(0xFFFFFFFFu, v, o));
    return v;
}
static __device__ __forceinline__ float warp_min(float v) {
    #pragma unroll
    for (int o = 16; o > 0; o >>= 1) v = fminf(v, __shfl_xor_sync(0xFFFFFFFFu, v, o));
    return v;
}

__global__ __launch_bounds__(256, 8)
void binnorm_kernel(const float* __restrict__ x, float* __restrict__ out, int B) {
    const int warp = threadIdx.x >> 5;
    const int lane = threadIdx.x & 31;
    const int row  = blockIdx.x * 8 + warp;
    if (row >= B) return;

    const float4* __restrict__ xr = reinterpret_cast<const float4*>(x + (size_t)row * BN_D);
    float4 v0 = xr[lane];        // elements [4*lane .. 4*lane+3]
    float4 v1 = xr[lane + 32];   // elements [128+4*lane .. +3]
    float xs[8] = {v0.x, v0.y, v0.z, v0.w, v1.x, v1.y, v1.z, v1.w};

    // Row stats: bracket endpoints + warm start.
    float mx = xs[0], mn = xs[0], sm = 0.f, sq = 0.f;
    #pragma unroll
    for (int i = 0; i < 8; ++i) {
        mx = fmaxf(mx, xs[i]);
        mn = fminf(mn, xs[i]);
        sm += xs[i];
        sq += xs[i] * xs[i];
    }
    mx = warp_max(mx);
    mn = warp_min(mn);
    sm = warp_sum(sm);
    sq = warp_sum(sq);

    float lo = -mx - 7.0f;             // f(lo) <= 256*sigmoid(-7) - 64 < 0
    float hi = -mn + 7.0f;             // f(hi) >= 256*sigmoid(+7) - 64 > 0
    const float m   = sm * (1.0f / BN_D);
    const float var = fmaxf(sq * (1.0f / BN_D) - m * m, 0.0f);
    // Probit warm start: E[sigmoid(X+nu)] ~ Phi(lam*(m+nu)/sqrt(1+lam^2 s^2)) = 1/4
    float nu = -m - 1.0763f * sqrtf(1.0f + 0.39270f * var);
    nu = fminf(fmaxf(nu, lo), hi);

    // Safeguarded Newton. f, fp are warp-uniform (butterfly reduction) ->
    // uniform branches, deterministic.
    #pragma unroll 1
    for (int it = 0; it < 20; ++it) {
        float f = 0.f, fp = 0.f;
        #pragma unroll
        for (int i = 0; i < 8; ++i) {
            float t = __expf(-(xs[i] + nu));           // e^{-z}
            float s = __fdividef(1.0f, 1.0f + t);      // sigmoid(z)
            f  += s;
            fp += s * s * t;                           // s*(1-s)
        }
        f  = warp_sum(f) - 64.0f;
        fp = warp_sum(fp);

        if (f < 0.f) lo = nu; else hi = nu;

        float nun = nu - f / fp;                       // fp>0; inf/nan falls to bisection
        if (!(nun > lo && nun < hi)) nun = 0.5f * (lo + hi);
        float d = fabsf(nun - nu);
        nu = nun;
        if (d < 2e-7f * fmaxf(1.0f, fabsf(nu))) break; // quadratic conv: residual ~1e-9
    }

    // Final accurate sigmoid(x + nu), written back coalesced as float4.
    float4* __restrict__ orow = reinterpret_cast<float4*>(out + (size_t)row * BN_D);
    float r[8];
    #pragma unroll
    for (int i = 0; i < 8; ++i) {
        float z = fminf(xs[i] + nu, 20.0f);            // guard exp overflow (never hits in practice)
        float e = __expf(z);
        r[i] = e * __fdividef(1.0f, 1.0f + e);         // rel-accurate for z<=0; abs-accurate for z>0
    }
    float4 o0 = make_float4(r[0], r[1], r[2], r[3]);
    float4 o1 = make_float4(r[4], r[5], r[6], r[7]);
    orow[lane]      = o0;
    orow[lane + 32] = o1;
}

extern "C" void kernel_launch(void* const* d_in, const int* in_sizes, int n_in,
                              void* d_out, int out_size) {
    const float* x = (const float*)d_in[0];
    float* out = (float*)d_out;
    const int B = in_sizes[0] / BN_D;        // 16384 rows of 256
    const int blocks = (B + 7) / 8;          // 8 rows (warps) per block
    binnorm_kernel<<<blocks, 256>>>(x, out, B);
}

// round 3
// speedup vs baseline: 3.4902x; 3.4902x over previous
#include <cuda_runtime.h>

// BinNormTrain: per-row nu s.t. sum_d sigmoid(x[d]+nu) == 64; out = sigmoid(x+nu).
// Safeguarded Newton, warp per row. R3 = R2 with the exp2 intrinsic fixed:
// inline PTX ex2.approx (MUFU) instead of the nonexistent __exp2f.

#ifndef BN_D
#define BN_D 256
#endif

static __device__ __forceinline__ float ex2_approx(float a) {
    float r;
    asm("ex2.approx.ftz.f32 %0, %1;" : "=f"(r) : "f"(a));
    return r;
}

static __device__ __forceinline__ float warp_sum(float v) {
    #pragma unroll
    for (int o = 16; o > 0; o >>= 1) v += __shfl_xor_sync(0xFFFFFFFFu, v, o);
    return v;  // bitwise-identical on all lanes
}
static __device__ __forceinline__ float warp_max(float v) {
    #pragma unroll
    for (int o = 16; o > 0; o >>= 1) v = fmaxf(v, __shfl_xor_sync(0xFFFFFFFFu, v, o));
    return v;
}
static __device__ __forceinline__ float warp_min(float v) {
    #pragma unroll
    for (int o = 16; o > 0; o >>= 1) v = fminf(v, __shfl_xor_sync(0xFFFFFFFFu, v, o));
    return v;
}

__global__ __launch_bounds__(256, 8)
void binnorm_kernel(const float* __restrict__ x, float* __restrict__ out, int B) {
    const int lane   = threadIdx.x & 31;
    const int warp0  = (blockIdx.x * blockDim.x + threadIdx.x) >> 5;
    const int nwarps = (gridDim.x * blockDim.x) >> 5;
    const float L2E = 1.44269504f;

    for (int row = warp0; row < B; row += nwarps) {
        const float4* __restrict__ xr = reinterpret_cast<const float4*>(x + (size_t)row * BN_D);
        float4 v0 = xr[lane];
        float4 v1 = xr[lane + 32];
        float xs[8] = {v0.x, v0.y, v0.z, v0.w, v1.x, v1.y, v1.z, v1.w};

        // Row stats -> bracket + warm start.
        float mx = xs[0], mn = xs[0], sm = 0.f, sq = 0.f;
        #pragma unroll
        for (int i = 0; i < 8; ++i) {
            mx = fmaxf(mx, xs[i]);
            mn = fminf(mn, xs[i]);
            sm += xs[i];
            sq = fmaf(xs[i], xs[i], sq);
        }
        mx = warp_max(mx); mn = warp_min(mn);
        sm = warp_sum(sm); sq = warp_sum(sq);

        float lo = -mx - 7.0f;              // f(lo) <= 256*sig(-7) - 64 < 0
        float hi = -mn + 7.0f;              // f(hi) >= 256*sig(+7) - 64 > 0
        const float m   = sm * (1.0f / BN_D);
        const float var = fmaxf(sq * (1.0f / BN_D) - m * m, 0.0f);
        // Logit-moment warm start: sig(u)=1/4 -> u=-ln3; nu ~ -m + u*sqrt(1+pi/8*var)
        float nu = -m - 1.0986123f * sqrtf(fmaf(0.3926991f, var, 1.0f));
        nu = fminf(fmaxf(nu, lo), hi);

        float r[8];
        #pragma unroll 1
        for (int it = 0; it < 16; ++it) {
            const float nl2e = -L2E * nu;   // t = 2^(-(x+nu)*L2E)
            float f = 0.f, q = 0.f;
            #pragma unroll
            for (int i = 0; i < 8; ++i) {
                float t = ex2_approx(fmaf(xs[i], -L2E, nl2e)); // e^{-(x+nu)}
                float s = __fdividef(1.0f, 1.0f + t);          // sigmoid
                r[i] = s;
                f += s;
                q = fmaf(s, s, q);
            }
            f = warp_sum(f);
            q = warp_sum(q);
            const float fp = f - q;         // sum s(1-s)  (~40, no cancellation)
            f -= 64.0f;

            if (f < 0.f) lo = nu; else hi = nu;

            float nun = nu - __fdividef(f, fp);
            if (!(nun > lo && nun < hi)) nun = 0.5f * (lo + hi);
            const float d = fabsf(nun - nu);
            nu = nun;
            if (d < 2e-4f) break;           // residual nu-err <~2e-4; gate is 1e-3
        }

        // Cached sigmoids are at a nu within 2e-4 of final -> inside tolerance.
        float4* __restrict__ orow = reinterpret_cast<float4*>(out + (size_t)row * BN_D);
        orow[lane]      = make_float4(r[0], r[1], r[2], r[3]);
        orow[lane + 32] = make_float4(r[4], r[5], r[6], r[7]);
    }
}

extern "C" void kernel_launch(void* const* d_in, const int* in_sizes, int n_in,
                              void* d_out, int out_size) {
    const float* x = (const float*)d_in[0];
    float* out = (float*)d_out;
    const int B = in_sizes[0] / BN_D;    // 16384 rows
    // 1024 blocks x 8 warps = 8192 warps -> exactly 2 rows/warp, single wave on 148 SMs.
    binnorm_kernel<<<1024, 256>>>(x, out, B);
}